// round 15
// baseline (speedup 1.0000x reference)
#include <cuda_runtime.h>
#include <cuda_bf16.h>
#include <math.h>

#define SEQ   8192
#define EMB   256
#define HID   128      // per-direction hidden
#define GATES 512      // 4*HID
#define NTAG  14
#define START 12
#define STOP  13
#define NEG   (-10000.0f)

// ---------------- scratch (device globals; no allocation) ----------------
__device__ float d_pre[2][SEQ][GATES];      // 32 MB: input projection + biases
__device__ float d_h[2][SEQ][HID];          // 8 MB
__device__ float d_feats[SEQ * 16];         // padded stride 16

// MUFU.TANH (single-instruction tanh, lat ~16; rel_err-validated in R14)
__device__ __forceinline__ float tanh_mufu(float x) {
    float y;
    asm("tanh.approx.f32 %0, %1;" : "=f"(y) : "f"(x));
    return y;
}
// sigmoid via MUFU.TANH: 1 MUFU + 1 FMA
__device__ __forceinline__ float sig_mufu(float x) {
    return fmaf(0.5f, tanh_mufu(0.5f * x), 0.5f);
}

// ---------------- kernel 1: input projection GEMM -------------------------
__global__ void __launch_bounds__(256) prep_kernel(
    const int* __restrict__ sent, const float* __restrict__ emb,
    const float* __restrict__ wih_f, const float* __restrict__ bih_f, const float* __restrict__ bhh_f,
    const float* __restrict__ wih_b, const float* __restrict__ bih_b, const float* __restrict__ bhh_b)
{
    const int dir = blockIdx.z;
    const float* wih = dir ? wih_b : wih_f;
    const float* bih = dir ? bih_b : bih_f;
    const float* bhh = dir ? bhh_b : bhh_f;
    const int t0 = blockIdx.x * 64;
    const int r0 = blockIdx.y * 64;

    __shared__ float xs[64][65];
    __shared__ float ws[64][65];
    __shared__ int   sidx[64];

    const int tid = threadIdx.x;
    if (tid < 64) {
        int t = t0 + tid;
        sidx[tid] = sent[dir ? (SEQ - 1 - t) : t];
    }

    const int tx = tid & 15;
    const int ty = tid >> 4;
    float acc[4][4];
    #pragma unroll
    for (int i = 0; i < 4; i++)
        #pragma unroll
        for (int j = 0; j < 4; j++) acc[i][j] = 0.f;

    for (int kc = 0; kc < EMB; kc += 64) {
        __syncthreads();
        #pragma unroll
        for (int e = 0; e < 16; e++) {
            int lin = e * 256 + tid;
            int kk  = lin & 63;
            int row = lin >> 6;
            xs[kk][row] = emb[(size_t)sidx[row] * EMB + kc + kk];
            ws[kk][row] = wih[(size_t)(r0 + row) * EMB + kc + kk];
        }
        __syncthreads();
        #pragma unroll 8
        for (int kk = 0; kk < 64; kk++) {
            float xv[4], wv[4];
            #pragma unroll
            for (int i = 0; i < 4; i++) xv[i] = xs[kk][tx + 16 * i];
            #pragma unroll
            for (int j = 0; j < 4; j++) wv[j] = ws[kk][ty + 16 * j];
            #pragma unroll
            for (int i = 0; i < 4; i++)
                #pragma unroll
                for (int j = 0; j < 4; j++) acc[i][j] += xv[i] * wv[j];
        }
    }

    #pragma unroll
    for (int i = 0; i < 4; i++) {
        int t = t0 + tx + 16 * i;
        #pragma unroll
        for (int j = 0; j < 4; j++) {
            int r = r0 + ty + 16 * j;
            d_pre[dir][t][r] = acc[i][j] + bih[r] + bhh[r];
        }
    }
}

// ---------------- kernel 2: sequential LSTM (8863 champion + compute cuts) -
// 2 CTAs (one per direction), 512 threads, one gate row per thread.
// 80 weight cols register-resident, 48-col tail in smem (float2-packed).
// smem-acts combine, 2 barriers/step. CHANGES vs champion: MUFU.TANH
// activations, 8 accumulators, float2 tail loads, no t=0 peel.
#define RW 80
#define TAILC (HID - RW)               // 48 tail columns
#define TAILP (TAILC / 2)              // 24 float2 pairs
#define LSTM_SMEM ((TAILP * GATES * 2 + HID + GATES) * 4)

__global__ void __launch_bounds__(GATES, 1) lstm_kernel(
    const float* __restrict__ whh_f, const float* __restrict__ whh_b)
{
    const int dir = blockIdx.x;
    const float* __restrict__ whh = dir ? whh_b : whh_f;
    const float* __restrict__ pre  = &d_pre[dir][0][0];
    float* __restrict__ hout = &d_h[dir][0][0];

    extern __shared__ float sm[];
    float2* Wt2  = (float2*)sm;                    // [TAILP][GATES]
    float*  hsm  = sm + TAILP * GATES * 2;         // [HID] (16B aligned)
    float*  acts = hsm + HID;                      // [GATES]

    const int r = threadIdx.x;
    const int g = r >> 7;                          // gate 0..3 — warp-uniform

    // register-resident weight head: whh[r][0..RW)
    float wreg[RW];
    {
        const float* wr = &whh[(size_t)r * HID];
        #pragma unroll
        for (int i = 0; i < RW / 4; i++) {
            float4 v = *(const float4*)&wr[i * 4];
            wreg[i*4+0] = v.x; wreg[i*4+1] = v.y; wreg[i*4+2] = v.z; wreg[i*4+3] = v.w;
        }
        // smem tail, float2-packed, transposed: Wt2[p][r] = (w[RW+2p], w[RW+2p+1])
        #pragma unroll
        for (int p = 0; p < TAILP; p++)
            Wt2[p * GATES + r] = make_float2(wr[RW + 2 * p], wr[RW + 2 * p + 1]);
    }

    if (r < HID) hsm[r] = 0.f;                     // t=0: matvec on zeros is exact
    float c = 0.f;
    __syncthreads();

    float pre_cur = pre[r];
    for (int t = 0; t < SEQ; t++) {
        float pre_nxt = 0.f;
        if (t + 1 < SEQ) pre_nxt = pre[(size_t)(t + 1) * GATES + r];

        float a0 = 0.f, a1 = 0.f, a2 = 0.f, a3 = 0.f;
        float a4 = 0.f, a5 = 0.f, a6 = 0.f, a7 = 0.f;

        // register head: 80 cols, 8 independent chains
        #pragma unroll
        for (int k = 0; k < RW; k += 8) {
            float4 h0 = *(const float4*)&hsm[k];
            float4 h1 = *(const float4*)&hsm[k + 4];
            a0 += wreg[k+0] * h0.x;
            a1 += wreg[k+1] * h0.y;
            a2 += wreg[k+2] * h0.z;
            a3 += wreg[k+3] * h0.w;
            a4 += wreg[k+4] * h1.x;
            a5 += wreg[k+5] * h1.y;
            a6 += wreg[k+6] * h1.z;
            a7 += wreg[k+7] * h1.w;
        }
        // smem tail: 48 cols as float2 weight loads
        #pragma unroll
        for (int k = 0; k < TAILC; k += 4) {
            float4 hv = *(const float4*)&hsm[RW + k];
            float2 w0 = Wt2[((k >> 1) + 0) * GATES + r];
            float2 w1 = Wt2[((k >> 1) + 1) * GATES + r];
            a0 += w0.x * hv.x;
            a1 += w0.y * hv.y;
            a2 += w1.x * hv.z;
            a3 += w1.y * hv.w;
        }
        float acc = pre_cur + (((a0 + a1) + (a2 + a3)) + ((a4 + a5) + (a6 + a7)));

        // MUFU activation (g warp-uniform: no divergence)
        acts[r] = (g == 2) ? tanh_mufu(acc) : sig_mufu(acc);
        __syncthreads();

        if (r < HID) {
            float iv = acts[r];
            float fv = acts[HID + r];
            float gv = acts[2 * HID + r];
            float ov = acts[3 * HID + r];
            c = fv * c + iv * gv;
            float h = ov * tanh_mufu(c);
            hsm[r] = h;
            hout[(size_t)t * HID + r] = h;
        }
        __syncthreads();
        pre_cur = pre_nxt;
    }
}

// ---------------- kernel 3: tag feats ------------------------------------
__global__ void __launch_bounds__(256) feats_kernel(
    const float* __restrict__ wtag, const float* __restrict__ btag)
{
    const int tid = threadIdx.x;
    const int n  = tid & 15;
    const int tl = tid >> 4;
    const int t  = blockIdx.x * 16 + tl;
    if (n >= NTAG) return;

    const float* __restrict__ hf = &d_h[0][t][0];
    const float* __restrict__ hb = &d_h[1][SEQ - 1 - t][0];
    const float* __restrict__ w  = &wtag[n * 256];

    float acc = btag[n];
    #pragma unroll 8
    for (int jj = 0; jj < HID; jj += 4) {
        float4 h4 = *(const float4*)&hf[jj];
        float4 w4 = *(const float4*)&w[jj];
        acc += h4.x * w4.x + h4.y * w4.y + h4.z * w4.z + h4.w * w4.w;
    }
    #pragma unroll 8
    for (int jj = 0; jj < HID; jj += 4) {
        float4 h4 = *(const float4*)&hb[jj];
        float4 w4 = *(const float4*)&w[HID + jj];
        acc += h4.x * w4.x + h4.y * w4.y + h4.z * w4.z + h4.w * w4.w;
    }
    d_feats[t * 16 + n] = acc;
}

// ---------------- kernel 4: Viterbi, register-resident fv ------------------
#define VCHUNK 512
#define NCHUNK (SEQ / VCHUNK)
#define VIT_SMEM (SEQ * 16 + 2 * VCHUNK * 16 * 4 + 64)

#define CMB(va, ia, vb, ib) { bool _gt = ((vb) > (va)); (va) = _gt ? (vb) : (va); (ia) = _gt ? (ib) : (ia); }

__global__ void __launch_bounds__(256, 1) viterbi_kernel(
    const float* __restrict__ trans, float* __restrict__ out)
{
    extern __shared__ unsigned char vsm[];
    unsigned char* bp = vsm;                                  // [SEQ][16]
    float* fbuf = (float*)(vsm + SEQ * 16);                   // [2][VCHUNK*16]
    float* fout = fbuf + 2 * VCHUNK * 16;                     // [16]

    const int tid  = threadIdx.x;
    const int warp = tid >> 5;
    const int lane = tid & 31;

    for (int i = tid; i < VCHUNK * 16; i += 256) fbuf[i] = d_feats[i];

    float fv = (lane == START) ? 0.f : NEG;
    float tr[NTAG];
    #pragma unroll
    for (int p = 0; p < NTAG; p++)
        tr[p] = (lane < NTAG) ? trans[lane * NTAG + p] : 0.f;
    __syncthreads();

    for (int ch = 0; ch < NCHUNK; ch++) {
        const int buf = ch & 1;
        if (warp > 0) {
            if (ch + 1 < NCHUNK) {
                const int nbuf = buf ^ 1;
                for (int i = tid - 32; i < VCHUNK * 16; i += 224)
                    fbuf[nbuf * VCHUNK * 16 + i] = d_feats[(ch + 1) * VCHUNK * 16 + i];
            }
        } else {
            const float* fb = fbuf + buf * VCHUNK * 16;
            for (int s = 0; s < VCHUNK; s++) {
                const int t = ch * VCHUNK + s;
                float sv[NTAG];
                #pragma unroll
                for (int p = 0; p < NTAG; p++)
                    sv[p] = __shfl_sync(0xffffffffu, fv, p) + tr[p];
                float v[7]; int ix[7];
                #pragma unroll
                for (int k = 0; k < 7; k++) {
                    bool gt = sv[2*k+1] > sv[2*k];
                    v[k]  = gt ? sv[2*k+1] : sv[2*k];
                    ix[k] = gt ? (2*k+1) : (2*k);
                }
                CMB(v[0], ix[0], v[1], ix[1]);
                CMB(v[2], ix[2], v[3], ix[3]);
                CMB(v[4], ix[4], v[5], ix[5]);
                CMB(v[0], ix[0], v[2], ix[2]);
                CMB(v[4], ix[4], v[6], ix[6]);
                CMB(v[0], ix[0], v[4], ix[4]);
                if (lane < NTAG) {
                    fv = v[0] + fb[s * 16 + lane];
                    bp[t * 16 + lane] = (unsigned char)ix[0];
                }
            }
        }
        __syncthreads();
    }

    if (warp == 0 && lane < NTAG) fout[lane] = fv;
    __syncthreads();

    if (tid == 0) {
        float best = fout[0] + trans[STOP * NTAG + 0]; int barg = 0;
        #pragma unroll
        for (int p = 1; p < NTAG; p++) {
            float sc = fout[p] + trans[STOP * NTAG + p];
            if (sc > best) { best = sc; barg = p; }
        }
        out[0] = best;
        int tag = barg;
        for (int t = SEQ - 1; t >= 0; t--) {
            out[1 + t] = (float)tag;
            tag = bp[t * 16 + tag];
        }
    }
}

// ---------------- launch ---------------------------------------------------
extern "C" void kernel_launch(void* const* d_in, const int* in_sizes, int n_in,
                              void* d_out, int out_size)
{
    const int*   sent  = (const int*)  d_in[0];
    const float* emb   = (const float*)d_in[1];
    const float* wih_f = (const float*)d_in[2];
    const float* whh_f = (const float*)d_in[3];
    const float* bih_f = (const float*)d_in[4];
    const float* bhh_f = (const float*)d_in[5];
    const float* wih_b = (const float*)d_in[6];
    const float* whh_b = (const float*)d_in[7];
    const float* bih_b = (const float*)d_in[8];
    const float* bhh_b = (const float*)d_in[9];
    const float* wtag  = (const float*)d_in[10];
    const float* btag  = (const float*)d_in[11];
    const float* trans = (const float*)d_in[12];
    float* out = (float*)d_out;

    cudaFuncSetAttribute(lstm_kernel,    cudaFuncAttributeMaxDynamicSharedMemorySize, LSTM_SMEM);
    cudaFuncSetAttribute(viterbi_kernel, cudaFuncAttributeMaxDynamicSharedMemorySize, VIT_SMEM);

    prep_kernel<<<dim3(SEQ / 64, GATES / 64, 2), 256>>>(
        sent, emb, wih_f, bih_f, bhh_f, wih_b, bih_b, bhh_b);
    lstm_kernel<<<2, GATES, LSTM_SMEM>>>(whh_f, whh_b);
    feats_kernel<<<SEQ / 16, 256>>>(wtag, btag);
    viterbi_kernel<<<1, 256, VIT_SMEM>>>(trans, out);
}

// round 16
// speedup vs baseline: 1.0288x; 1.0288x over previous
#include <cuda_runtime.h>
#include <cuda_bf16.h>
#include <math.h>

#define SEQ   8192
#define EMB   256
#define HID   128      // per-direction hidden
#define GATES 512      // 4*HID
#define NTAG  14
#define START 12
#define STOP  13
#define NEG   (-10000.0f)

// ---------------- scratch (device globals; no allocation) ----------------
__device__ float d_pre[2][SEQ][GATES];      // 32 MB: input projection + biases
__device__ float d_h[2][SEQ][HID];          // 8 MB: hidden states (dir1 in reversed-step order)
__device__ float d_feats[SEQ * 16];         // padded stride 16

// MUFU.TANH (single-instruction tanh; rel_err-validated R14/R15)
__device__ __forceinline__ float tanh_mufu(float x) {
    float y;
    asm("tanh.approx.f32 %0, %1;" : "=f"(y) : "f"(x));
    return y;
}
// sigmoid via MUFU.TANH: 1 MUFU + 1 FMA + 1 MUL
__device__ __forceinline__ float sig_mufu(float x) {
    return fmaf(0.5f, tanh_mufu(0.5f * x), 0.5f);
}

// ---------------- kernel 1: input projection GEMM -------------------------
__global__ void __launch_bounds__(256) prep_kernel(
    const int* __restrict__ sent, const float* __restrict__ emb,
    const float* __restrict__ wih_f, const float* __restrict__ bih_f, const float* __restrict__ bhh_f,
    const float* __restrict__ wih_b, const float* __restrict__ bih_b, const float* __restrict__ bhh_b)
{
    const int dir = blockIdx.z;
    const float* wih = dir ? wih_b : wih_f;
    const float* bih = dir ? bih_b : bih_f;
    const float* bhh = dir ? bhh_b : bhh_f;
    const int t0 = blockIdx.x * 64;
    const int r0 = blockIdx.y * 64;

    __shared__ float xs[64][65];   // [k][t], padded
    __shared__ float ws[64][65];   // [k][r], padded
    __shared__ int   sidx[64];

    const int tid = threadIdx.x;
    if (tid < 64) {
        int t = t0 + tid;
        sidx[tid] = sent[dir ? (SEQ - 1 - t) : t];
    }

    const int tx = tid & 15;       // t sub-index
    const int ty = tid >> 4;       // r sub-index
    float acc[4][4];
    #pragma unroll
    for (int i = 0; i < 4; i++)
        #pragma unroll
        for (int j = 0; j < 4; j++) acc[i][j] = 0.f;

    for (int kc = 0; kc < EMB; kc += 64) {
        __syncthreads();
        #pragma unroll
        for (int e = 0; e < 16; e++) {
            int lin = e * 256 + tid;          // 0..4095
            int kk  = lin & 63;
            int row = lin >> 6;
            xs[kk][row] = emb[(size_t)sidx[row] * EMB + kc + kk];
            ws[kk][row] = wih[(size_t)(r0 + row) * EMB + kc + kk];
        }
        __syncthreads();
        #pragma unroll 8
        for (int kk = 0; kk < 64; kk++) {
            float xv[4], wv[4];
            #pragma unroll
            for (int i = 0; i < 4; i++) xv[i] = xs[kk][tx + 16 * i];
            #pragma unroll
            for (int j = 0; j < 4; j++) wv[j] = ws[kk][ty + 16 * j];
            #pragma unroll
            for (int i = 0; i < 4; i++)
                #pragma unroll
                for (int j = 0; j < 4; j++) acc[i][j] += xv[i] * wv[j];
        }
    }

    #pragma unroll
    for (int i = 0; i < 4; i++) {
        int t = t0 + tx + 16 * i;
        #pragma unroll
        for (int j = 0; j < 4; j++) {
            int r = r0 + ty + 16 * j;
            d_pre[dir][t][r] = acc[i][j] + bih[r] + bhh[r];
        }
    }
}

// ---------------- kernel 2: sequential LSTM (one block per direction) -----
// EXACT 8863-champion structure; ONLY the activations are MUFU now.
#define RW 80                         // weight columns held in registers
#define SW (HID - RW)                 // 48 columns from smem
#define LSTM_SMEM ((SW * GATES + HID + GATES) * 4)

__global__ void __launch_bounds__(GATES, 1) lstm_kernel(
    const float* __restrict__ whh_f, const float* __restrict__ whh_b)
{
    const int dir = blockIdx.x;
    const float* __restrict__ whh = dir ? whh_b : whh_f;
    const float* __restrict__ pre = &d_pre[dir][0][0];
    float* __restrict__ hout = &d_h[dir][0][0];

    extern __shared__ float sm[];
    float* Wt   = sm;                      // [SW][GATES] transposed tail weights
    float* hsm  = sm + SW * GATES;         // [HID]
    float* gbuf = hsm + HID;               // [GATES]

    const int r = threadIdx.x;

    // register-resident weight head: whh[r][0..RW)
    float wreg[RW];
    #pragma unroll
    for (int i = 0; i < RW / 4; i++) {
        float4 v = *(const float4*)&whh[(size_t)r * HID + i * 4];
        wreg[i*4+0] = v.x; wreg[i*4+1] = v.y; wreg[i*4+2] = v.z; wreg[i*4+3] = v.w;
    }
    // smem tail, transposed for conflict-free reads: Wt[k][r] = whh[r][RW+k]
    #pragma unroll
    for (int i = 0; i < SW; i++) Wt[i * GATES + r] = whh[(size_t)r * HID + RW + i];

    if (r < HID) hsm[r] = 0.f;
    float c = 0.f;
    __syncthreads();

    float pre_next = pre[r];   // t = 0
    for (int t = 0; t < SEQ; t++) {
        float acc = pre_next;
        if (t + 1 < SEQ) pre_next = pre[(size_t)(t + 1) * GATES + r];

        float a0 = 0.f, a1 = 0.f, a2 = 0.f, a3 = 0.f;
        #pragma unroll
        for (int k = 0; k < RW; k += 4) {
            float4 hv = *(const float4*)&hsm[k];
            a0 += wreg[k+0] * hv.x;
            a1 += wreg[k+1] * hv.y;
            a2 += wreg[k+2] * hv.z;
            a3 += wreg[k+3] * hv.w;
        }
        #pragma unroll
        for (int k = 0; k < SW; k += 4) {
            float4 hv = *(const float4*)&hsm[RW + k];
            a0 += Wt[(k+0) * GATES + r] * hv.x;
            a1 += Wt[(k+1) * GATES + r] * hv.y;
            a2 += Wt[(k+2) * GATES + r] * hv.z;
            a3 += Wt[(k+3) * GATES + r] * hv.w;
        }
        acc += (a0 + a1) + (a2 + a3);
        gbuf[r] = acc;
        __syncthreads();

        if (r < HID) {
            float ig = sig_mufu(gbuf[r]);
            float fg = sig_mufu(gbuf[HID + r]);
            float gg = tanh_mufu(gbuf[2 * HID + r]);
            float og = sig_mufu(gbuf[3 * HID + r]);
            c = fg * c + ig * gg;
            float h = og * tanh_mufu(c);
            hsm[r] = h;
            hout[(size_t)t * HID + r] = h;
        }
        __syncthreads();
    }
}

// ---------------- kernel 3: tag feats ------------------------------------
__global__ void __launch_bounds__(256) feats_kernel(
    const float* __restrict__ wtag, const float* __restrict__ btag)
{
    const int tid = threadIdx.x;
    const int n  = tid & 15;
    const int tl = tid >> 4;
    const int t  = blockIdx.x * 16 + tl;
    if (n >= NTAG) return;

    const float* __restrict__ hf = &d_h[0][t][0];
    const float* __restrict__ hb = &d_h[1][SEQ - 1 - t][0];
    const float* __restrict__ w  = &wtag[n * 256];

    float acc = btag[n];
    #pragma unroll 8
    for (int j = 0; j < HID; j += 4) {
        float4 h4 = *(const float4*)&hf[j];
        float4 w4 = *(const float4*)&w[j];
        acc += h4.x * w4.x + h4.y * w4.y + h4.z * w4.z + h4.w * w4.w;
    }
    #pragma unroll 8
    for (int j = 0; j < HID; j += 4) {
        float4 h4 = *(const float4*)&hb[j];
        float4 w4 = *(const float4*)&w[HID + j];
        acc += h4.x * w4.x + h4.y * w4.y + h4.z * w4.z + h4.w * w4.w;
    }
    d_feats[t * 16 + n] = acc;
}

// ---------------- kernel 4: Viterbi (sequential, tree argmax) -------------
#define VCHUNK 512
#define NCHUNK (SEQ / VCHUNK)
#define VIT_SMEM (SEQ * 16 + 2 * VCHUNK * 16 * 4 + 64)

// ordered combine: pick right only if STRICTLY greater (first-max semantics)
#define CMB(va, ia, vb, ib) { bool _gt = ((vb) > (va)); (va) = _gt ? (vb) : (va); (ia) = _gt ? (ib) : (ia); }

__global__ void __launch_bounds__(256, 1) viterbi_kernel(
    const float* __restrict__ trans, float* __restrict__ out)
{
    extern __shared__ unsigned char vsm[];
    unsigned char* bp = vsm;                                  // [SEQ][16]
    float* fbuf = (float*)(vsm + SEQ * 16);                   // [2][VCHUNK*16]
    float* fvs  = fbuf + 2 * VCHUNK * 16;                     // [16]

    const int tid  = threadIdx.x;
    const int warp = tid >> 5;

    for (int i = tid; i < VCHUNK * 16; i += 256) fbuf[i] = d_feats[i];
    if (tid < 16) fvs[tid] = (tid == START) ? 0.f : NEG;

    float tr[NTAG];
    if (tid < NTAG) {
        #pragma unroll
        for (int p = 0; p < NTAG; p++) tr[p] = trans[tid * NTAG + p];
    }
    __syncthreads();

    for (int ch = 0; ch < NCHUNK; ch++) {
        const int buf = ch & 1;
        if (warp > 0) {
            if (ch + 1 < NCHUNK) {
                const int nbuf = buf ^ 1;
                for (int i = tid - 32; i < VCHUNK * 16; i += 224)
                    fbuf[nbuf * VCHUNK * 16 + i] = d_feats[(ch + 1) * VCHUNK * 16 + i];
            }
        } else {
            const float* fb = fbuf + buf * VCHUNK * 16;
            for (int s = 0; s < VCHUNK; s++) {
                const int t = ch * VCHUNK + s;
                float best = 0.f; int barg = 0;
                if (tid < NTAG) {
                    float sv[14];
                    #pragma unroll
                    for (int p = 0; p < NTAG; p++) sv[p] = fvs[p] + tr[p];
                    float v[7]; int ix[7];
                    #pragma unroll
                    for (int k = 0; k < 7; k++) {
                        bool gt = sv[2*k+1] > sv[2*k];
                        v[k]  = gt ? sv[2*k+1] : sv[2*k];
                        ix[k] = gt ? (2*k+1) : (2*k);
                    }
                    CMB(v[0], ix[0], v[1], ix[1]);
                    CMB(v[2], ix[2], v[3], ix[3]);
                    CMB(v[4], ix[4], v[5], ix[5]);
                    CMB(v[0], ix[0], v[2], ix[2]);
                    CMB(v[4], ix[4], v[6], ix[6]);
                    CMB(v[0], ix[0], v[4], ix[4]);
                    best = v[0] + fb[s * 16 + tid];
                    barg = ix[0];
                }
                __syncwarp();
                if (tid < NTAG) {
                    fvs[tid] = best;
                    bp[t * 16 + tid] = (unsigned char)barg;
                }
                __syncwarp();
            }
        }
        __syncthreads();
    }

    if (tid == 0) {
        float best = fvs[0] + trans[STOP * NTAG + 0]; int barg = 0;
        #pragma unroll
        for (int p = 1; p < NTAG; p++) {
            float sc = fvs[p] + trans[STOP * NTAG + p];
            if (sc > best) { best = sc; barg = p; }
        }
        out[0] = best;
        int tag = barg;
        for (int t = SEQ - 1; t >= 0; t--) {
            out[1 + t] = (float)tag;
            tag = bp[t * 16 + tag];
        }
    }
}

// ---------------- launch ---------------------------------------------------
extern "C" void kernel_launch(void* const* d_in, const int* in_sizes, int n_in,
                              void* d_out, int out_size)
{
    const int*   sent  = (const int*)  d_in[0];
    const float* emb   = (const float*)d_in[1];
    const float* wih_f = (const float*)d_in[2];
    const float* whh_f = (const float*)d_in[3];
    const float* bih_f = (const float*)d_in[4];
    const float* bhh_f = (const float*)d_in[5];
    const float* wih_b = (const float*)d_in[6];
    const float* whh_b = (const float*)d_in[7];
    const float* bih_b = (const float*)d_in[8];
    const float* bhh_b = (const float*)d_in[9];
    const float* wtag  = (const float*)d_in[10];
    const float* btag  = (const float*)d_in[11];
    const float* trans = (const float*)d_in[12];
    float* out = (float*)d_out;

    cudaFuncSetAttribute(lstm_kernel,    cudaFuncAttributeMaxDynamicSharedMemorySize, LSTM_SMEM);
    cudaFuncSetAttribute(viterbi_kernel, cudaFuncAttributeMaxDynamicSharedMemorySize, VIT_SMEM);

    prep_kernel<<<dim3(SEQ / 64, GATES / 64, 2), 256>>>(
        sent, emb, wih_f, bih_f, bhh_f, wih_b, bih_b, bhh_b);
    lstm_kernel<<<2, GATES, LSTM_SMEM>>>(whh_f, whh_b);
    feats_kernel<<<SEQ / 16, 256>>>(wtag, btag);
    viterbi_kernel<<<1, 256, VIT_SMEM>>>(trans, out);
}

// round 17
// speedup vs baseline: 1.0834x; 1.0530x over previous
#include <cuda_runtime.h>
#include <cuda_bf16.h>
#include <math.h>

#define SEQ   8192
#define EMB   256
#define HID   128      // per-direction hidden
#define GATES 512      // 4*HID
#define NTAG  14
#define START 12
#define STOP  13
#define NEG   (-10000.0f)

// ---------------- scratch (device globals; no allocation) ----------------
__device__ float d_pre[2][SEQ][GATES];      // 32 MB: input projection + biases
__device__ float d_h[2][SEQ][HID];          // 8 MB: hidden states (dir1 in reversed-step order)
__device__ float d_feats[SEQ * 16];         // padded stride 16

// MUFU.TANH (single-instruction tanh; rel_err-validated R14/R15/R16)
__device__ __forceinline__ float tanh_mufu(float x) {
    float y;
    asm("tanh.approx.f32 %0, %1;" : "=f"(y) : "f"(x));
    return y;
}
// sigmoid via MUFU.TANH: 1 MUFU + 1 FMA
__device__ __forceinline__ float sig_mufu(float x) {
    return fmaf(0.5f, tanh_mufu(0.5f * x), 0.5f);
}

// ---------------- kernel 1: input projection GEMM -------------------------
__global__ void __launch_bounds__(256) prep_kernel(
    const int* __restrict__ sent, const float* __restrict__ emb,
    const float* __restrict__ wih_f, const float* __restrict__ bih_f, const float* __restrict__ bhh_f,
    const float* __restrict__ wih_b, const float* __restrict__ bih_b, const float* __restrict__ bhh_b)
{
    const int dir = blockIdx.z;
    const float* wih = dir ? wih_b : wih_f;
    const float* bih = dir ? bih_b : bih_f;
    const float* bhh = dir ? bhh_b : bhh_f;
    const int t0 = blockIdx.x * 64;
    const int r0 = blockIdx.y * 64;

    __shared__ float xs[64][65];   // [k][t], padded
    __shared__ float ws[64][65];   // [k][r], padded
    __shared__ int   sidx[64];

    const int tid = threadIdx.x;
    if (tid < 64) {
        int t = t0 + tid;
        sidx[tid] = sent[dir ? (SEQ - 1 - t) : t];
    }

    const int tx = tid & 15;       // t sub-index
    const int ty = tid >> 4;       // r sub-index
    float acc[4][4];
    #pragma unroll
    for (int i = 0; i < 4; i++)
        #pragma unroll
        for (int j = 0; j < 4; j++) acc[i][j] = 0.f;

    for (int kc = 0; kc < EMB; kc += 64) {
        __syncthreads();
        #pragma unroll
        for (int e = 0; e < 16; e++) {
            int lin = e * 256 + tid;          // 0..4095
            int kk  = lin & 63;
            int row = lin >> 6;
            xs[kk][row] = emb[(size_t)sidx[row] * EMB + kc + kk];
            ws[kk][row] = wih[(size_t)(r0 + row) * EMB + kc + kk];
        }
        __syncthreads();
        #pragma unroll 8
        for (int kk = 0; kk < 64; kk++) {
            float xv[4], wv[4];
            #pragma unroll
            for (int i = 0; i < 4; i++) xv[i] = xs[kk][tx + 16 * i];
            #pragma unroll
            for (int j = 0; j < 4; j++) wv[j] = ws[kk][ty + 16 * j];
            #pragma unroll
            for (int i = 0; i < 4; i++)
                #pragma unroll
                for (int j = 0; j < 4; j++) acc[i][j] += xv[i] * wv[j];
        }
    }

    #pragma unroll
    for (int i = 0; i < 4; i++) {
        int t = t0 + tx + 16 * i;
        #pragma unroll
        for (int j = 0; j < 4; j++) {
            int r = r0 + ty + 16 * j;
            d_pre[dir][t][r] = acc[i][j] + bih[r] + bhh[r];
        }
    }
}

// ---------------- kernel 2: sequential LSTM (one block per direction) -----
// 512 threads, one gate row per thread. RW=96 weight cols in registers,
// 32-col tail in smem (crossbar traffic: 512 cyc/step vs 768 at RW=80).
// Gate activations pre-barrier on all 512 threads (MUFU). 2 barriers/step.
#define RW 96                         // weight columns held in registers
#define SW (HID - RW)                 // 32 columns from smem
#define LSTM_SMEM ((SW * GATES + HID + GATES) * 4)

__global__ void __launch_bounds__(GATES, 1) lstm_kernel(
    const float* __restrict__ whh_f, const float* __restrict__ whh_b)
{
    const int dir = blockIdx.x;
    const float* __restrict__ whh = dir ? whh_b : whh_f;
    const float* __restrict__ pre = &d_pre[dir][0][0];
    float* __restrict__ hout = &d_h[dir][0][0];

    extern __shared__ float sm[];
    float* Wt   = sm;                      // [SW][GATES] transposed tail weights
    float* hsm  = sm + SW * GATES;         // [HID]
    float* acts = hsm + HID;               // [GATES] post-activation gates

    const int r = threadIdx.x;
    const int g = r >> 7;                  // gate 0..3 — warp-uniform

    // register-resident weight head: whh[r][0..RW)
    float wreg[RW];
    #pragma unroll
    for (int i = 0; i < RW / 4; i++) {
        float4 v = *(const float4*)&whh[(size_t)r * HID + i * 4];
        wreg[i*4+0] = v.x; wreg[i*4+1] = v.y; wreg[i*4+2] = v.z; wreg[i*4+3] = v.w;
    }
    // smem tail, transposed for conflict-free reads: Wt[k][r] = whh[r][RW+k]
    #pragma unroll
    for (int i = 0; i < SW; i++) Wt[i * GATES + r] = whh[(size_t)r * HID + RW + i];

    if (r < HID) hsm[r] = 0.f;             // t=0: matvec on zeros is exact
    float c = 0.f;
    __syncthreads();

    float pre_next = pre[r];   // t = 0
    for (int t = 0; t < SEQ; t++) {
        float acc = pre_next;
        if (t + 1 < SEQ) pre_next = pre[(size_t)(t + 1) * GATES + r];

        float a0 = 0.f, a1 = 0.f, a2 = 0.f, a3 = 0.f;
        #pragma unroll
        for (int k = 0; k < RW; k += 4) {
            float4 hv = *(const float4*)&hsm[k];
            a0 += wreg[k+0] * hv.x;
            a1 += wreg[k+1] * hv.y;
            a2 += wreg[k+2] * hv.z;
            a3 += wreg[k+3] * hv.w;
        }
        #pragma unroll
        for (int k = 0; k < SW; k += 4) {
            float4 hv = *(const float4*)&hsm[RW + k];
            a0 += Wt[(k+0) * GATES + r] * hv.x;
            a1 += Wt[(k+1) * GATES + r] * hv.y;
            a2 += Wt[(k+2) * GATES + r] * hv.z;
            a3 += Wt[(k+3) * GATES + r] * hv.w;
        }
        acc += (a0 + a1) + (a2 + a3);

        // own-row activation on all 512 threads (g warp-uniform, no divergence)
        acts[r] = (g == 2) ? tanh_mufu(acc) : sig_mufu(acc);
        __syncthreads();

        if (r < HID) {
            float iv = acts[r];
            float fv = acts[HID + r];
            float gv = acts[2 * HID + r];
            float ov = acts[3 * HID + r];
            c = fv * c + iv * gv;
            float h = ov * tanh_mufu(c);
            hsm[r] = h;
            hout[(size_t)t * HID + r] = h;
        }
        __syncthreads();
    }
}

// ---------------- kernel 3: tag feats ------------------------------------
__global__ void __launch_bounds__(256) feats_kernel(
    const float* __restrict__ wtag, const float* __restrict__ btag)
{
    const int tid = threadIdx.x;
    const int n  = tid & 15;
    const int tl = tid >> 4;
    const int t  = blockIdx.x * 16 + tl;
    if (n >= NTAG) return;

    const float* __restrict__ hf = &d_h[0][t][0];
    const float* __restrict__ hb = &d_h[1][SEQ - 1 - t][0];
    const float* __restrict__ w  = &wtag[n * 256];

    float acc = btag[n];
    #pragma unroll 8
    for (int j = 0; j < HID; j += 4) {
        float4 h4 = *(const float4*)&hf[j];
        float4 w4 = *(const float4*)&w[j];
        acc += h4.x * w4.x + h4.y * w4.y + h4.z * w4.z + h4.w * w4.w;
    }
    #pragma unroll 8
    for (int j = 0; j < HID; j += 4) {
        float4 h4 = *(const float4*)&hb[j];
        float4 w4 = *(const float4*)&w[HID + j];
        acc += h4.x * w4.x + h4.y * w4.y + h4.z * w4.z + h4.w * w4.w;
    }
    d_feats[t * 16 + n] = acc;
}

// ---------------- kernel 4: Viterbi (sequential, tree argmax) -------------
#define VCHUNK 512
#define NCHUNK (SEQ / VCHUNK)
#define VIT_SMEM (SEQ * 16 + 2 * VCHUNK * 16 * 4 + 64)

// ordered combine: pick right only if STRICTLY greater (first-max semantics)
#define CMB(va, ia, vb, ib) { bool _gt = ((vb) > (va)); (va) = _gt ? (vb) : (va); (ia) = _gt ? (ib) : (ia); }

__global__ void __launch_bounds__(256, 1) viterbi_kernel(
    const float* __restrict__ trans, float* __restrict__ out)
{
    extern __shared__ unsigned char vsm[];
    unsigned char* bp = vsm;                                  // [SEQ][16]
    float* fbuf = (float*)(vsm + SEQ * 16);                   // [2][VCHUNK*16]
    float* fvs  = fbuf + 2 * VCHUNK * 16;                     // [16]

    const int tid  = threadIdx.x;
    const int warp = tid >> 5;

    for (int i = tid; i < VCHUNK * 16; i += 256) fbuf[i] = d_feats[i];
    if (tid < 16) fvs[tid] = (tid == START) ? 0.f : NEG;

    float tr[NTAG];
    if (tid < NTAG) {
        #pragma unroll
        for (int p = 0; p < NTAG; p++) tr[p] = trans[tid * NTAG + p];
    }
    __syncthreads();

    for (int ch = 0; ch < NCHUNK; ch++) {
        const int buf = ch & 1;
        if (warp > 0) {
            if (ch + 1 < NCHUNK) {
                const int nbuf = buf ^ 1;
                for (int i = tid - 32; i < VCHUNK * 16; i += 224)
                    fbuf[nbuf * VCHUNK * 16 + i] = d_feats[(ch + 1) * VCHUNK * 16 + i];
            }
        } else {
            const float* fb = fbuf + buf * VCHUNK * 16;
            for (int s = 0; s < VCHUNK; s++) {
                const int t = ch * VCHUNK + s;
                float best = 0.f; int barg = 0;
                if (tid < NTAG) {
                    float sv[14];
                    #pragma unroll
                    for (int p = 0; p < NTAG; p++) sv[p] = fvs[p] + tr[p];
                    float v[7]; int ix[7];
                    #pragma unroll
                    for (int k = 0; k < 7; k++) {
                        bool gt = sv[2*k+1] > sv[2*k];
                        v[k]  = gt ? sv[2*k+1] : sv[2*k];
                        ix[k] = gt ? (2*k+1) : (2*k);
                    }
                    CMB(v[0], ix[0], v[1], ix[1]);
                    CMB(v[2], ix[2], v[3], ix[3]);
                    CMB(v[4], ix[4], v[5], ix[5]);
                    CMB(v[0], ix[0], v[2], ix[2]);
                    CMB(v[4], ix[4], v[6], ix[6]);
                    CMB(v[0], ix[0], v[4], ix[4]);
                    best = v[0] + fb[s * 16 + tid];
                    barg = ix[0];
                }
                __syncwarp();
                if (tid < NTAG) {
                    fvs[tid] = best;
                    bp[t * 16 + tid] = (unsigned char)barg;
                }
                __syncwarp();
            }
        }
        __syncthreads();
    }

    if (tid == 0) {
        float best = fvs[0] + trans[STOP * NTAG + 0]; int barg = 0;
        #pragma unroll
        for (int p = 1; p < NTAG; p++) {
            float sc = fvs[p] + trans[STOP * NTAG + p];
            if (sc > best) { best = sc; barg = p; }
        }
        out[0] = best;
        int tag = barg;
        for (int t = SEQ - 1; t >= 0; t--) {
            out[1 + t] = (float)tag;
            tag = bp[t * 16 + tag];
        }
    }
}

// ---------------- launch ---------------------------------------------------
extern "C" void kernel_launch(void* const* d_in, const int* in_sizes, int n_in,
                              void* d_out, int out_size)
{
    const int*   sent  = (const int*)  d_in[0];
    const float* emb   = (const float*)d_in[1];
    const float* wih_f = (const float*)d_in[2];
    const float* whh_f = (const float*)d_in[3];
    const float* bih_f = (const float*)d_in[4];
    const float* bhh_f = (const float*)d_in[5];
    const float* wih_b = (const float*)d_in[6];
    const float* whh_b = (const float*)d_in[7];
    const float* bih_b = (const float*)d_in[8];
    const float* bhh_b = (const float*)d_in[9];
    const float* wtag  = (const float*)d_in[10];
    const float* btag  = (const float*)d_in[11];
    const float* trans = (const float*)d_in[12];
    float* out = (float*)d_out;

    cudaFuncSetAttribute(lstm_kernel,    cudaFuncAttributeMaxDynamicSharedMemorySize, LSTM_SMEM);
    cudaFuncSetAttribute(viterbi_kernel, cudaFuncAttributeMaxDynamicSharedMemorySize, VIT_SMEM);

    prep_kernel<<<dim3(SEQ / 64, GATES / 64, 2), 256>>>(
        sent, emb, wih_f, bih_f, bhh_f, wih_b, bih_b, bhh_b);
    lstm_kernel<<<2, GATES, LSTM_SMEM>>>(whh_f, whh_b);
    feats_kernel<<<SEQ / 16, 256>>>(wtag, btag);
    viterbi_kernel<<<1, 256, VIT_SMEM>>>(trans, out);
}